// round 12
// baseline (speedup 1.0000x reference)
#include <cuda_runtime.h>
#include <cuda_fp16.h>
#include <cstdint>
#include <cstddef>

#define E_   8
#define T_   2048
#define DIN_ 2048
#define H_   1408

#define HTILES 11
#define DTILES 16
#define TTILES 16
#define KC1 64          // DIN_/32  (K32 fragment tiles)
#define KC2 44          // H_/32

// fragment-major fp16 tiles, in uint32 units (one u32 = half2)
#define ATILE_U 2048    // 128(M) x 32(K) fp16 A tile = 8KB
#define BTILE_U 2048    // 128(N) x 32(K) fp16 B tile = 8KB

// ---------------- device scratch (allocation-free) ----------------
__device__ uint32_t g_wfG[(size_t)E_ * HTILES * KC1 * ATILE_U];
__device__ uint32_t g_wfD[(size_t)E_ * HTILES * KC1 * ATILE_U];
__device__ uint32_t g_wfU[(size_t)E_ * DTILES * KC2 * ATILE_U];
__device__ uint32_t g_xf [(size_t)E_ * TTILES * KC1 * BTILE_U];
__device__ uint32_t g_hf [(size_t)E_ * TTILES * KC2 * BTILE_U];

// ---------------- helpers ----------------
__device__ __forceinline__ uint32_t smem_u32(const void* p) {
    uint32_t a;
    asm("{ .reg .u64 t; cvta.to.shared.u64 t, %1; cvt.u32.u64 %0, t; }" : "=r"(a) : "l"(p));
    return a;
}
__device__ __forceinline__ uint32_t pack2(float lo, float hi) {
    __half2 h = __floats2half2_rn(lo, hi);
    return *(const uint32_t*)&h;
}
__device__ __forceinline__ void cp16(uint32_t s, const void* g) {
    asm volatile("cp.async.cg.shared.global [%0], [%1], 16;" :: "r"(s), "l"(g));
}
#define CP_COMMIT() asm volatile("cp.async.commit_group;" ::: "memory")
#define CP_WAIT(n)  asm volatile("cp.async.wait_group %0;" :: "n"(n) : "memory")

// m16n8k16 fp16 row.col, fp32 accum
__device__ __forceinline__ void mma16(float* cc, const uint4& a, const uint2& b) {
    asm volatile(
        "mma.sync.aligned.m16n8k16.row.col.f32.f16.f16.f32 "
        "{%0,%1,%2,%3}, {%4,%5,%6,%7}, {%8,%9}, {%0,%1,%2,%3};"
        : "+f"(cc[0]), "+f"(cc[1]), "+f"(cc[2]), "+f"(cc[3])
        : "r"(a.x), "r"(a.y), "r"(a.z), "r"(a.w), "r"(b.x), "r"(b.y));
}

// ---------------- prep: src[K][M] fp32 -> A-frag fp16 tiles (float4 loads) --
__global__ void prep_w_kernel(const float* __restrict__ src, uint4* __restrict__ dst,
                              int R, int C, int Mtiles, int Kchunks) {
    __shared__ float ts[32][132];
    int e = blockIdx.z, mt = blockIdx.y, kc = blockIdx.x;
    int tid = threadIdx.x;
    const float* sp = src + (size_t)e * R * C + (size_t)(kc * 32) * C + mt * 128;
#pragma unroll
    for (int i = 0; i < 4; i++) {
        int idx = tid + i * 256;            // 0..1023 float4s
        int kk = idx >> 5, j = idx & 31;
        float4 v = *(const float4*)(sp + (size_t)kk * C + 4 * j);
        *(float4*)&ts[kk][4 * j] = v;
    }
    __syncthreads();
    uint4* dp = dst + ((size_t)(e * Mtiles + mt) * Kchunks + kc) * 512;
#pragma unroll
    for (int i = 0; i < 2; i++) {
        int f = tid + i * 256;
        int lane = f & 31, ks = (f >> 5) & 1, mb = f >> 6;
        int r = lane >> 2, c = lane & 3;
        int kb = ks * 16 + 2 * c;
        int m0 = mb * 16 + r;
        uint4 v;
        v.x = pack2(ts[kb][m0],     ts[kb + 1][m0]);
        v.y = pack2(ts[kb][m0 + 8], ts[kb + 1][m0 + 8]);
        v.z = pack2(ts[kb + 8][m0],     ts[kb + 9][m0]);
        v.w = pack2(ts[kb + 8][m0 + 8], ts[kb + 9][m0 + 8]);
        dp[f] = v;
    }
}

// ---------------- prep: x[t][k] fp32 -> B-frag fp16 tiles (float4 loads) ----
__global__ void prep_x_kernel(const float* __restrict__ src, uint2* __restrict__ dst) {
    __shared__ float ts[128][36];
    int e = blockIdx.z, tb = blockIdx.y, kc = blockIdx.x;
    int tid = threadIdx.x;
    const float* sp = src + (size_t)e * T_ * DIN_ + (size_t)(tb * 128) * DIN_ + kc * 32;
#pragma unroll
    for (int i = 0; i < 4; i++) {
        int idx = tid + i * 256;            // 0..1023 float4s
        int tt = idx >> 3, j = idx & 7;
        float4 v = *(const float4*)(sp + (size_t)tt * DIN_ + 4 * j);
        *(float4*)&ts[tt][4 * j] = v;
    }
    __syncthreads();
    uint2* dp = dst + ((size_t)(e * TTILES + tb) * KC1 + kc) * 1024;
#pragma unroll
    for (int i = 0; i < 4; i++) {
        int f = tid + i * 256;
        int lane = f & 31, ks = (f >> 5) & 1, n8 = f >> 6;
        int rl = lane >> 2, c = lane & 3;
        int tt = n8 * 8 + rl, kb = ks * 16 + 2 * c;
        uint2 v;
        v.x = pack2(ts[tt][kb],     ts[tt][kb + 1]);
        v.y = pack2(ts[tt][kb + 8], ts[tt][kb + 9]);
        dp[f] = v;
    }
}

// ---------------- k1: fused gate+down GEMM + SwiGLU, warp-specialized -------
// 512 threads: warps 0-7 gate, warps 8-15 down; each 2(M)x4(N) grid, 64x32 tile.
// Shared 3-stage pipeline (Ag 8KB + Ad 8KB + B 8KB = 24KB/stage, 72KB total),
// one barrier per K32 chunk. SwiGLU via fp32 smem exchange (reuses pipe smem).
#define K1_STAGE_U 6144
__global__ __launch_bounds__(512, 1) void k1_gemm(const uint32_t* __restrict__ xf,
                                                  const uint32_t* __restrict__ gF,
                                                  const uint32_t* __restrict__ dF,
                                                  uint32_t* __restrict__ hf) {
    extern __shared__ uint32_t sm[];
    int tid = threadIdx.x, lane = tid & 31, wid = tid >> 5;
    int grp = wid >> 3;                 // 0 = gate warps, 1 = down warps
    int w = wid & 7;
    int wm = w & 1, wn = w >> 1;        // 2(M) x 4(N), warp tile 64x32
    int r = lane >> 2, c = lane & 3;

    int bid = blockIdx.x;
    int e = bid / (HTILES * TTILES);
    int rem = bid % (HTILES * TTILES);
    int ht = rem >> 4;
    int tb = rem & 15;
    int h0 = ht * 128;

    const uint32_t* gp = gF + ((size_t)(e * HTILES + ht) * KC1) * ATILE_U;
    const uint32_t* dp = dF + ((size_t)(e * HTILES + ht) * KC1) * ATILE_U;
    const uint32_t* xp = xf + ((size_t)(e * TTILES + tb) * KC1) * BTILE_U;

    float acc[4][4][4];                 // 64 floats
#pragma unroll
    for (int mt = 0; mt < 4; mt++)
#pragma unroll
        for (int nt = 0; nt < 4; nt++)
#pragma unroll
            for (int k = 0; k < 4; k++) acc[mt][nt][k] = 0.f;

    uint32_t sbase = smem_u32(sm);

    auto fill = [&](int s, int kc) {    // kc = K32 chunk index
        uint32_t stb = sbase + (uint32_t)(s * K1_STAGE_U * 4);
        const uint4* ga = (const uint4*)(gp + (size_t)kc * ATILE_U);
        const uint4* da = (const uint4*)(dp + (size_t)kc * ATILE_U);
        const uint4* xa = (const uint4*)(xp + (size_t)kc * BTILE_U);
#pragma unroll
        for (int i = 0; i < 3; i++) {
            int idx = tid + i * 512;                 // 0..1535 uint4s
            if (idx < 512)       cp16(stb + idx * 16, ga + idx);
            else if (idx < 1024) cp16(stb + idx * 16, da + (idx - 512));
            else                 cp16(stb + idx * 16, xa + (idx - 1024));
        }
    };

    auto compute = [&](int s) {
        const uint32_t* stg = sm + s * K1_STAGE_U;
        const uint4* A = (const uint4*)(stg + (grp ? 2048 : 0));  // Ad : Ag
        const uint2* B = (const uint2*)(stg + 4096);
#pragma unroll
        for (int ks = 0; ks < 2; ks++) {
            uint2 bf[4];
#pragma unroll
            for (int nt = 0; nt < 4; nt++)
                bf[nt] = B[((wn * 4 + nt) * 2 + ks) * 32 + lane];
            uint4 af[4];
#pragma unroll
            for (int mt = 0; mt < 4; mt++)
                af[mt] = A[((wm * 4 + mt) * 2 + ks) * 32 + lane];
#pragma unroll
            for (int mt = 0; mt < 4; mt++)
#pragma unroll
                for (int nt = 0; nt < 4; nt++) mma16(acc[mt][nt], af[mt], bf[nt]);
        }
    };

    // 3-stage pipeline, one barrier per chunk
    fill(0, 0); CP_COMMIT();
    fill(1, 1); CP_COMMIT();
    for (int kc = 0; kc < KC1; kc++) {
        if (kc == KC1 - 1) { CP_WAIT(0); } else { CP_WAIT(1); }
        __syncthreads();
        compute(kc % 3);
        if (kc + 2 < KC1) { fill((kc + 2) % 3, kc + 2); CP_COMMIT(); }
    }

    // ---- SwiGLU epilogue: gate warps -> smem fp32 exchange; down warps pack.
    __syncthreads();                    // all MMAs done; pipe smem reusable
    float* ex = (float*)sm;             // 128 x 132 fp32 = 67584 B (< 72KB)
    if (grp == 0) {
#pragma unroll
        for (int mt = 0; mt < 4; mt++)
#pragma unroll
            for (int nt = 0; nt < 4; nt++)
#pragma unroll
                for (int q = 0; q < 4; q++) {
                    int hl = wm * 64 + mt * 16 + r + (q >> 1) * 8;
                    int tl = (wn * 4 + nt) * 8 + 2 * c + (q & 1);
                    ex[hl * 132 + tl] = acc[mt][nt][q];
                }
    }
    __syncthreads();
    if (grp == 1) {
        uint32_t* hb = hf + ((size_t)(e * TTILES + tb) * KC2) * BTILE_U;
#pragma unroll
        for (int mt = 0; mt < 4; mt++) {
            int kc2 = (h0 >> 5) + wm * 2 + (mt >> 1);
            int ks2 = mt & 1;
            uint32_t* base = hb + (size_t)kc2 * BTILE_U;
#pragma unroll
            for (int nt = 0; nt < 4; nt++) {
                int n8 = wn * 4 + nt;
#pragma unroll
                for (int q = 0; q < 4; q++) {
                    int hl = wm * 64 + mt * 16 + r + (q >> 1) * 8;
                    int tl = (wn * 4 + nt) * 8 + 2 * c + (q & 1);
                    float g = ex[hl * 132 + tl];
                    float u = acc[mt][nt][q];
                    float v = g / (1.0f + __expf(-g)) * u;
                    float pv = __shfl_xor_sync(0xffffffffu, v, 4);   // partner r^1
                    if (!(r & 1)) {
                        int lane2 = (2 * c + (q & 1)) * 4 + (r >> 1);
                        int fidx = (n8 * 2 + ks2) * 32 + lane2;
                        base[fidx * 2 + (q >> 1)] = pack2(v, pv);
                    }
                }
            }
        }
    }
}

// ---------------- k2: out[t,d] = sum_h h[t,h] * up[h,d]  (R11 version) -----
#define K2_STAGE_U 4096
__global__ __launch_bounds__(256, 2) void k2_gemm(const uint32_t* __restrict__ hf,
                                                  const uint32_t* __restrict__ uF,
                                                  float* __restrict__ out) {
    extern __shared__ uint32_t sm[];
    int tid = threadIdx.x, lane = tid & 31, wid = tid >> 5;
    int wm = wid & 1, wn = wid >> 1;
    int r = lane >> 2, c = lane & 3;

    int bid = blockIdx.x;
    int e = bid / (DTILES * TTILES);
    int rem = bid % (DTILES * TTILES);
    int dt = rem >> 4;
    int tb = rem & 15;
    int d0 = dt * 128, t0 = tb * 128;

    const uint32_t* up = uF + ((size_t)(e * DTILES + dt) * KC2) * ATILE_U;
    const uint32_t* hp = hf + ((size_t)(e * TTILES + tb) * KC2) * BTILE_U;

    float acc[4][4][4];
#pragma unroll
    for (int mt = 0; mt < 4; mt++)
#pragma unroll
        for (int nt = 0; nt < 4; nt++)
#pragma unroll
            for (int k = 0; k < 4; k++) acc[mt][nt][k] = 0.f;

    uint32_t sbase = smem_u32(sm);

    auto fill = [&](int s, int kc) {
        uint32_t stb = sbase + (uint32_t)(s * K2_STAGE_U * 4);
        const uint4* ua = (const uint4*)(up + (size_t)kc * ATILE_U);
        const uint4* ha = (const uint4*)(hp + (size_t)kc * BTILE_U);
#pragma unroll
        for (int i = 0; i < 4; i++) {
            int idx = tid + i * 256;                 // 0..1023 uint4s
            if (idx < 512) cp16(stb + idx * 16, ua + idx);
            else           cp16(stb + idx * 16, ha + (idx - 512));
        }
    };

    auto compute = [&](int s) {
        const uint32_t* stg = sm + s * K2_STAGE_U;
        const uint4* A = (const uint4*)stg;
        const uint2* B = (const uint2*)(stg + 2048);
#pragma unroll
        for (int ks = 0; ks < 2; ks++) {
            uint2 bf[4];
#pragma unroll
            for (int nt = 0; nt < 4; nt++)
                bf[nt] = B[((wn * 4 + nt) * 2 + ks) * 32 + lane];
            uint4 af[4];
#pragma unroll
            for (int mt = 0; mt < 4; mt++)
                af[mt] = A[((wm * 4 + mt) * 2 + ks) * 32 + lane];
#pragma unroll
            for (int mt = 0; mt < 4; mt++)
#pragma unroll
                for (int nt = 0; nt < 4; nt++) mma16(acc[mt][nt], af[mt], bf[nt]);
        }
    };

    fill(0, 0); CP_COMMIT();
    fill(1, 1); CP_COMMIT();
    for (int kc = 0; kc < KC2; kc++) {
        if (kc == KC2 - 1) { CP_WAIT(0); } else { CP_WAIT(1); }
        __syncthreads();
        compute(kc % 3);
        if (kc + 2 < KC2) { fill((kc + 2) % 3, kc + 2); CP_COMMIT(); }
    }

    float* ob = out + (size_t)e * T_ * DIN_;
#pragma unroll
    for (int mt = 0; mt < 4; mt++)
#pragma unroll
        for (int nt = 0; nt < 4; nt++) {
            int t = t0 + (wn * 4 + nt) * 8 + 2 * c;
#pragma unroll
            for (int h2 = 0; h2 < 2; h2++) {
                int dg = d0 + wm * 64 + mt * 16 + r + h2 * 8;
                ob[(size_t)t * DIN_ + dg]       = acc[mt][nt][h2 * 2 + 0];
                ob[(size_t)(t + 1) * DIN_ + dg] = acc[mt][nt][h2 * 2 + 1];
            }
        }
}

// ---------------- launch ----------------
extern "C" void kernel_launch(void* const* d_in, const int* in_sizes, int n_in,
                              void* d_out, int out_size) {
    const float* x    = (const float*)d_in[0];
    const float* gate = (const float*)d_in[1];
    const float* down = (const float*)d_in[2];
    const float* up   = (const float*)d_in[3];
    float* out = (float*)d_out;

    uint32_t *gF, *dF, *uF, *xF, *hF;
    cudaGetSymbolAddress((void**)&gF, g_wfG);
    cudaGetSymbolAddress((void**)&dF, g_wfD);
    cudaGetSymbolAddress((void**)&uF, g_wfU);
    cudaGetSymbolAddress((void**)&xF, g_xf);
    cudaGetSymbolAddress((void**)&hF, g_hf);

    const int k1_smem = 3 * K1_STAGE_U * 4;   // 73728
    const int k2_smem = 3 * K2_STAGE_U * 4;   // 49152 (x2 CTAs = 96KB/SM)
    cudaFuncSetAttribute(k1_gemm, cudaFuncAttributeMaxDynamicSharedMemorySize, k1_smem);
    cudaFuncSetAttribute(k2_gemm, cudaFuncAttributeMaxDynamicSharedMemorySize, k2_smem);

    // keep k1 at launch index 3 (ncu's profiled slot)
    prep_w_kernel<<<dim3(KC1, HTILES, E_), 256>>>(gate, (uint4*)gF, DIN_, H_, HTILES, KC1);
    prep_w_kernel<<<dim3(KC1, HTILES, E_), 256>>>(down, (uint4*)dF, DIN_, H_, HTILES, KC1);
    prep_x_kernel<<<dim3(KC1, TTILES, E_), 256>>>(x, (uint2*)xF);
    k1_gemm<<<E_ * HTILES * TTILES, 512, k1_smem>>>(xF, gF, dF, hF);
    prep_w_kernel<<<dim3(KC2, DTILES, E_), 256>>>(up, (uint4*)uF, H_, DIN_, DTILES, KC2);
    k2_gemm<<<E_ * DTILES * TTILES, 256, k2_smem>>>(hF, uF, out);
}

// round 13
// speedup vs baseline: 1.1371x; 1.1371x over previous
#include <cuda_runtime.h>
#include <cuda_fp16.h>
#include <cstdint>
#include <cstddef>

#define E_   8
#define T_   2048
#define DIN_ 2048
#define H_   1408

#define HTILES 11
#define DTILES 16
#define TTILES 16
#define KC1 64          // DIN_/32  (32-K fragment tiles)
#define KC2 44          // H_/32
#define NCH1 32         // DIN_/64  (64-K chunks for k1)

// fragment-major fp16 tiles, in uint32 units (one u32 = half2)
#define ATILE_U 2048    // 128(M) x 32(K) fp16 A tile = 8KB
#define BTILE_U 2048    // 128(N) x 32(K) fp16 B tile = 8KB

// ---------------- device scratch (allocation-free) ----------------
__device__ uint32_t g_wfG[(size_t)E_ * HTILES * KC1 * ATILE_U];
__device__ uint32_t g_wfD[(size_t)E_ * HTILES * KC1 * ATILE_U];
__device__ uint32_t g_wfU[(size_t)E_ * DTILES * KC2 * ATILE_U];
__device__ uint32_t g_xf [(size_t)E_ * TTILES * KC1 * BTILE_U];
__device__ uint32_t g_hf [(size_t)E_ * TTILES * KC2 * BTILE_U];

// ---------------- helpers ----------------
__device__ __forceinline__ uint32_t smem_u32(const void* p) {
    uint32_t a;
    asm("{ .reg .u64 t; cvta.to.shared.u64 t, %1; cvt.u32.u64 %0, t; }" : "=r"(a) : "l"(p));
    return a;
}
__device__ __forceinline__ uint32_t pack2(float lo, float hi) {
    __half2 h = __floats2half2_rn(lo, hi);
    return *(const uint32_t*)&h;
}
__device__ __forceinline__ void cp16(uint32_t s, const void* g) {
    asm volatile("cp.async.cg.shared.global [%0], [%1], 16;" :: "r"(s), "l"(g));
}
#define CP_COMMIT() asm volatile("cp.async.commit_group;" ::: "memory")
#define CP_WAIT(n)  asm volatile("cp.async.wait_group %0;" :: "n"(n) : "memory")

// m16n8k16 fp16 row.col, fp32 accum
__device__ __forceinline__ void mma16(float* cc, const uint4& a, const uint2& b) {
    asm volatile(
        "mma.sync.aligned.m16n8k16.row.col.f32.f16.f16.f32 "
        "{%0,%1,%2,%3}, {%4,%5,%6,%7}, {%8,%9}, {%0,%1,%2,%3};"
        : "+f"(cc[0]), "+f"(cc[1]), "+f"(cc[2]), "+f"(cc[3])
        : "r"(a.x), "r"(a.y), "r"(a.z), "r"(a.w), "r"(b.x), "r"(b.y));
}

// ---------------- prep: src[K][M] fp32 -> A-frag fp16 tiles (float4 loads) --
__global__ void prep_w_kernel(const float* __restrict__ src, uint4* __restrict__ dst,
                              int R, int C, int Mtiles, int Kchunks) {
    __shared__ float ts[32][132];
    int e = blockIdx.z, mt = blockIdx.y, kc = blockIdx.x;
    int tid = threadIdx.x;
    const float* sp = src + (size_t)e * R * C + (size_t)(kc * 32) * C + mt * 128;
#pragma unroll
    for (int i = 0; i < 4; i++) {
        int idx = tid + i * 256;            // 0..1023 float4s
        int kk = idx >> 5, j = idx & 31;
        float4 v = *(const float4*)(sp + (size_t)kk * C + 4 * j);
        *(float4*)&ts[kk][4 * j] = v;
    }
    __syncthreads();
    uint4* dp = dst + ((size_t)(e * Mtiles + mt) * Kchunks + kc) * 512;
#pragma unroll
    for (int i = 0; i < 2; i++) {
        int f = tid + i * 256;
        int lane = f & 31, ks = (f >> 5) & 1, mb = f >> 6;
        int r = lane >> 2, c = lane & 3;
        int kb = ks * 16 + 2 * c;
        int m0 = mb * 16 + r;
        uint4 v;
        v.x = pack2(ts[kb][m0],     ts[kb + 1][m0]);
        v.y = pack2(ts[kb][m0 + 8], ts[kb + 1][m0 + 8]);
        v.z = pack2(ts[kb + 8][m0],     ts[kb + 9][m0]);
        v.w = pack2(ts[kb + 8][m0 + 8], ts[kb + 9][m0 + 8]);
        dp[f] = v;
    }
}

// ---------------- prep: x[t][k] fp32 -> B-frag fp16 tiles (float4 loads) ----
__global__ void prep_x_kernel(const float* __restrict__ src, uint2* __restrict__ dst) {
    __shared__ float ts[128][36];
    int e = blockIdx.z, tb = blockIdx.y, kc = blockIdx.x;
    int tid = threadIdx.x;
    const float* sp = src + (size_t)e * T_ * DIN_ + (size_t)(tb * 128) * DIN_ + kc * 32;
#pragma unroll
    for (int i = 0; i < 4; i++) {
        int idx = tid + i * 256;            // 0..1023 float4s
        int tt = idx >> 3, j = idx & 7;
        float4 v = *(const float4*)(sp + (size_t)tt * DIN_ + 4 * j);
        *(float4*)&ts[tt][4 * j] = v;
    }
    __syncthreads();
    uint2* dp = dst + ((size_t)(e * TTILES + tb) * KC1 + kc) * 1024;
#pragma unroll
    for (int i = 0; i < 4; i++) {
        int f = tid + i * 256;
        int lane = f & 31, ks = (f >> 5) & 1, n8 = f >> 6;
        int rl = lane >> 2, c = lane & 3;
        int tt = n8 * 8 + rl, kb = ks * 16 + 2 * c;
        uint2 v;
        v.x = pack2(ts[tt][kb],     ts[tt][kb + 1]);
        v.y = pack2(ts[tt][kb + 8], ts[tt][kb + 9]);
        dp[f] = v;
    }
}

// ---------------- k1: fused gate+down GEMM + SwiGLU -> h frag (fp16) --------
// 256 threads, warp grid 2(M)x4(N), warp tile 64x32 per GEMM, K-chunk 64.
// 3-stage cp.async pipeline, ONE barrier per chunk, FILL ISSUED BEFORE COMPUTE.
// smem per stage: Ag(16KB) Ad(16KB) B(16KB) = 48KB; 3 stages = 144KB
#define K1_STAGE_U 12288
__global__ __launch_bounds__(256, 1) void k1_gemm(const uint32_t* __restrict__ xf,
                                                  const uint32_t* __restrict__ gF,
                                                  const uint32_t* __restrict__ dF,
                                                  uint32_t* __restrict__ hf) {
    extern __shared__ uint32_t sm[];
    int tid = threadIdx.x, lane = tid & 31, wid = tid >> 5;
    int wm = wid & 1, wn = wid >> 1;        // 2(M) x 4(N), warp tile 64x32
    int r = lane >> 2, c = lane & 3;

    int bid = blockIdx.x;
    int e = bid / (HTILES * TTILES);
    int rem = bid % (HTILES * TTILES);
    int ht = rem >> 4;
    int tb = rem & 15;
    int h0 = ht * 128;

    const uint32_t* gp = gF + ((size_t)(e * HTILES + ht) * KC1) * ATILE_U;
    const uint32_t* dp = dF + ((size_t)(e * HTILES + ht) * KC1) * ATILE_U;
    const uint32_t* xp = xf + ((size_t)(e * TTILES + tb) * KC1) * BTILE_U;

    float ag[4][4][4], ad[4][4][4];
#pragma unroll
    for (int mt = 0; mt < 4; mt++)
#pragma unroll
        for (int nt = 0; nt < 4; nt++)
#pragma unroll
            for (int k = 0; k < 4; k++) { ag[mt][nt][k] = 0.f; ad[mt][nt][k] = 0.f; }

    uint32_t sbase = smem_u32(sm);

    auto fill = [&](int s, int kc) {   // kc = 64-K chunk index, s = stage 0..2
        uint32_t stb = sbase + (uint32_t)(s * K1_STAGE_U * 4);
        const uint4* ga = (const uint4*)(gp + (size_t)(2 * kc) * ATILE_U);
        const uint4* da = (const uint4*)(dp + (size_t)(2 * kc) * ATILE_U);
        const uint4* xa = (const uint4*)(xp + (size_t)(2 * kc) * BTILE_U);
#pragma unroll
        for (int i = 0; i < 12; i++) {
            int idx = tid + i * 256;                 // 0..3071 uint4s
            if (idx < 1024)       cp16(stb + idx * 16, ga + idx);
            else if (idx < 2048)  cp16(stb + idx * 16, da + (idx - 1024));
            else                  cp16(stb + idx * 16, xa + (idx - 2048));
        }
    };

    auto compute = [&](int s) {
        const uint32_t* stg = sm + s * K1_STAGE_U;
        const uint4* Ag = (const uint4*)stg;               // 1024 uint4 (2 K32 subtiles)
        const uint4* Ad = (const uint4*)(stg + 4096);
        const uint2* Bx = (const uint2*)(stg + 8192);      // 2048 uint2

        // Preload ALL B fragments for the K64 chunk (4 steps x 4 nt = 32 regs)
        uint2 bf[4][4];
#pragma unroll
        for (int st = 0; st < 4; st++) {
            int kt = st >> 1, ks = st & 1;
#pragma unroll
            for (int nt = 0; nt < 4; nt++)
                bf[st][nt] = Bx[kt * 1024 + ((wn * 4 + nt) * 2 + ks) * 32 + lane];
        }
        // Preload gate-A for step 0
        uint4 aG[4], aD[4];
#pragma unroll
        for (int mt = 0; mt < 4; mt++)
            aG[mt] = Ag[((wm * 4 + mt) * 2 + 0) * 32 + lane];

#pragma unroll
        for (int st = 0; st < 4; st++) {
            int kt = st >> 1, ks = st & 1;
#pragma unroll
            for (int mt = 0; mt < 4; mt++)
                aD[mt] = Ad[kt * 512 + ((wm * 4 + mt) * 2 + ks) * 32 + lane];
#pragma unroll
            for (int mt = 0; mt < 4; mt++)
#pragma unroll
                for (int nt = 0; nt < 4; nt++) mma16(ag[mt][nt], aG[mt], bf[st][nt]);
            if (st < 3) {
                int st2 = st + 1, kt2 = st2 >> 1, ks2 = st2 & 1;
#pragma unroll
                for (int mt = 0; mt < 4; mt++)
                    aG[mt] = Ag[kt2 * 512 + ((wm * 4 + mt) * 2 + ks2) * 32 + lane];
            }
#pragma unroll
            for (int mt = 0; mt < 4; mt++)
#pragma unroll
                for (int nt = 0; nt < 4; nt++) mma16(ad[mt][nt], aD[mt], bf[st][nt]);
        }
    };

    // 3-stage pipeline, one barrier per chunk, fill issued BEFORE compute.
    // Safety: fill targets (kc+2)%3 == stage of chunk kc-1; every thread passed
    // compute(kc-1) before barrier(kc), so overwrite after the barrier is race-free.
    fill(0, 0); CP_COMMIT();
    fill(1, 1); CP_COMMIT();
    for (int kc = 0; kc < NCH1; kc++) {
        if (kc >= NCH1 - 1) { CP_WAIT(0); } else { CP_WAIT(1); }
        __syncthreads();
        if (kc + 2 < NCH1) { fill((kc + 2) % 3, kc + 2); CP_COMMIT(); }
        compute(kc % 3);
    }

    // SwiGLU epilogue -> hf in k2 B-frag fp16 layout (validated R7-R11).
    uint32_t* hb = hf + ((size_t)(e * TTILES + tb) * KC2) * BTILE_U;
#pragma unroll
    for (int mt = 0; mt < 4; mt++) {
        int kc2 = (h0 >> 5) + wm * 2 + (mt >> 1);
        int ks2 = mt & 1;
        uint32_t* base = hb + (size_t)kc2 * BTILE_U;
#pragma unroll
        for (int nt = 0; nt < 4; nt++) {
            int n8 = wn * 4 + nt;
#pragma unroll
            for (int q = 0; q < 4; q++) {
                float g = ag[mt][nt][q], u = ad[mt][nt][q];
                float v = g / (1.0f + __expf(-g)) * u;
                float pv = __shfl_xor_sync(0xffffffffu, v, 4);   // partner: r^1
                if (!(r & 1)) {
                    int lane2 = (2 * c + (q & 1)) * 4 + (r >> 1);
                    int fidx = (n8 * 2 + ks2) * 32 + lane2;
                    base[fidx * 2 + (q >> 1)] = pack2(v, pv);
                }
            }
        }
    }
}

// ---------------- k2: out[t,d] = sum_h h[t,h] * up[h,d] --------------------
// 256 threads, 2(M)x4(N) grid, warp tile 64x32, K-chunk 32, occ 2, 3-stage,
// fill issued before compute.
#define K2_STAGE_U 4096
__global__ __launch_bounds__(256, 2) void k2_gemm(const uint32_t* __restrict__ hf,
                                                  const uint32_t* __restrict__ uF,
                                                  float* __restrict__ out) {
    extern __shared__ uint32_t sm[];
    int tid = threadIdx.x, lane = tid & 31, wid = tid >> 5;
    int wm = wid & 1, wn = wid >> 1;
    int r = lane >> 2, c = lane & 3;

    int bid = blockIdx.x;
    int e = bid / (DTILES * TTILES);
    int rem = bid % (DTILES * TTILES);
    int dt = rem >> 4;
    int tb = rem & 15;
    int d0 = dt * 128, t0 = tb * 128;

    const uint32_t* up = uF + ((size_t)(e * DTILES + dt) * KC2) * ATILE_U;
    const uint32_t* hp = hf + ((size_t)(e * TTILES + tb) * KC2) * BTILE_U;

    float acc[4][4][4];
#pragma unroll
    for (int mt = 0; mt < 4; mt++)
#pragma unroll
        for (int nt = 0; nt < 4; nt++)
#pragma unroll
            for (int k = 0; k < 4; k++) acc[mt][nt][k] = 0.f;

    uint32_t sbase = smem_u32(sm);

    auto fill = [&](int s, int kc) {
        uint32_t stb = sbase + (uint32_t)(s * K2_STAGE_U * 4);
        const uint4* ua = (const uint4*)(up + (size_t)kc * ATILE_U);
        const uint4* ha = (const uint4*)(hp + (size_t)kc * BTILE_U);
#pragma unroll
        for (int i = 0; i < 4; i++) {
            int idx = tid + i * 256;                 // 0..1023 uint4s
            if (idx < 512) cp16(stb + idx * 16, ua + idx);
            else           cp16(stb + idx * 16, ha + (idx - 512));
        }
    };

    auto compute = [&](int s) {
        const uint32_t* stg = sm + s * K2_STAGE_U;
        const uint4* A = (const uint4*)stg;
        const uint2* B = (const uint2*)(stg + 2048);
#pragma unroll
        for (int ks = 0; ks < 2; ks++) {
            uint2 bf[4];
#pragma unroll
            for (int nt = 0; nt < 4; nt++)
                bf[nt] = B[((wn * 4 + nt) * 2 + ks) * 32 + lane];
            uint4 af[4];
#pragma unroll
            for (int mt = 0; mt < 4; mt++)
                af[mt] = A[((wm * 4 + mt) * 2 + ks) * 32 + lane];
#pragma unroll
            for (int mt = 0; mt < 4; mt++)
#pragma unroll
                for (int nt = 0; nt < 4; nt++) mma16(acc[mt][nt], af[mt], bf[nt]);
        }
    };

    fill(0, 0); CP_COMMIT();
    fill(1, 1); CP_COMMIT();
    for (int kc = 0; kc < KC2; kc++) {
        if (kc >= KC2 - 1) { CP_WAIT(0); } else { CP_WAIT(1); }
        __syncthreads();
        if (kc + 2 < KC2) { fill((kc + 2) % 3, kc + 2); CP_COMMIT(); }
        compute(kc % 3);
    }

    float* ob = out + (size_t)e * T_ * DIN_;
#pragma unroll
    for (int mt = 0; mt < 4; mt++)
#pragma unroll
        for (int nt = 0; nt < 4; nt++) {
            int t = t0 + (wn * 4 + nt) * 8 + 2 * c;
#pragma unroll
            for (int h2 = 0; h2 < 2; h2++) {
                int dg = d0 + wm * 64 + mt * 16 + r + h2 * 8;
                ob[(size_t)t * DIN_ + dg]       = acc[mt][nt][h2 * 2 + 0];
                ob[(size_t)(t + 1) * DIN_ + dg] = acc[mt][nt][h2 * 2 + 1];
            }
        }
}

// ---------------- launch ----------------
extern "C" void kernel_launch(void* const* d_in, const int* in_sizes, int n_in,
                              void* d_out, int out_size) {
    const float* x    = (const float*)d_in[0];
    const float* gate = (const float*)d_in[1];
    const float* down = (const float*)d_in[2];
    const float* up   = (const float*)d_in[3];
    float* out = (float*)d_out;

    uint32_t *gF, *dF, *uF, *xF, *hF;
    cudaGetSymbolAddress((void**)&gF, g_wfG);
    cudaGetSymbolAddress((void**)&dF, g_wfD);
    cudaGetSymbolAddress((void**)&uF, g_wfU);
    cudaGetSymbolAddress((void**)&xF, g_xf);
    cudaGetSymbolAddress((void**)&hF, g_hf);

    const int k1_smem = 3 * K1_STAGE_U * 4;   // 147456
    const int k2_smem = 3 * K2_STAGE_U * 4;   // 49152 (x2 CTAs = 96KB/SM)
    cudaFuncSetAttribute(k1_gemm, cudaFuncAttributeMaxDynamicSharedMemorySize, k1_smem);
    cudaFuncSetAttribute(k2_gemm, cudaFuncAttributeMaxDynamicSharedMemorySize, k2_smem);

    // keep k1 at launch index 3 (ncu's profiled slot)
    prep_w_kernel<<<dim3(KC1, HTILES, E_), 256>>>(gate, (uint4*)gF, DIN_, H_, HTILES, KC1);
    prep_w_kernel<<<dim3(KC1, HTILES, E_), 256>>>(down, (uint4*)dF, DIN_, H_, HTILES, KC1);
    prep_x_kernel<<<dim3(KC1, TTILES, E_), 256>>>(x, (uint2*)xF);
    k1_gemm<<<E_ * HTILES * TTILES, 256, k1_smem>>>(xF, gF, dF, hF);
    prep_w_kernel<<<dim3(KC2, DTILES, E_), 256>>>(up, (uint4*)uF, H_, DIN_, DTILES, KC2);
    k2_gemm<<<E_ * DTILES * TTILES, 256, k2_smem>>>(hF, uF, out);
}

// round 14
// speedup vs baseline: 1.2032x; 1.0581x over previous
#include <cuda_runtime.h>
#include <cuda_fp16.h>
#include <cstdint>
#include <cstddef>

#define E_   8
#define T_   2048
#define DIN_ 2048
#define H_   1408

#define HTILES 11
#define DTILES 16
#define TTILES 16
#define KC1 64          // DIN_/32  (32-K fragment tiles)
#define KC2 44          // H_/32
#define NCH1 32         // DIN_/64  (64-K chunks for k1)

// fragment-major fp16 tiles, in uint32 units (one u32 = half2)
#define ATILE_U 2048    // 128(M) x 32(K) fp16 A tile = 8KB
#define BTILE_U 2048    // 128(N) x 32(K) fp16 B tile = 8KB

// ---------------- device scratch (allocation-free) ----------------
__device__ uint32_t g_wfG[(size_t)E_ * HTILES * KC1 * ATILE_U];
__device__ uint32_t g_wfD[(size_t)E_ * HTILES * KC1 * ATILE_U];
__device__ uint32_t g_wfU[(size_t)E_ * DTILES * KC2 * ATILE_U];
__device__ uint32_t g_xf [(size_t)E_ * TTILES * KC1 * BTILE_U];
__device__ uint32_t g_hf [(size_t)E_ * TTILES * KC2 * BTILE_U];

// ---------------- helpers ----------------
__device__ __forceinline__ uint32_t smem_u32(const void* p) {
    uint32_t a;
    asm("{ .reg .u64 t; cvta.to.shared.u64 t, %1; cvt.u32.u64 %0, t; }" : "=r"(a) : "l"(p));
    return a;
}
__device__ __forceinline__ uint32_t pack2(float lo, float hi) {
    __half2 h = __floats2half2_rn(lo, hi);
    return *(const uint32_t*)&h;
}
__device__ __forceinline__ void cp16(uint32_t s, const void* g) {
    asm volatile("cp.async.cg.shared.global [%0], [%1], 16;" :: "r"(s), "l"(g));
}
#define CP_COMMIT() asm volatile("cp.async.commit_group;" ::: "memory")
#define CP_WAIT(n)  asm volatile("cp.async.wait_group %0;" :: "n"(n) : "memory")

// m16n8k16 fp16 row.col, fp32 accum
__device__ __forceinline__ void mma16(float* cc, const uint4& a, const uint2& b) {
    asm volatile(
        "mma.sync.aligned.m16n8k16.row.col.f32.f16.f16.f32 "
        "{%0,%1,%2,%3}, {%4,%5,%6,%7}, {%8,%9}, {%0,%1,%2,%3};"
        : "+f"(cc[0]), "+f"(cc[1]), "+f"(cc[2]), "+f"(cc[3])
        : "r"(a.x), "r"(a.y), "r"(a.z), "r"(a.w), "r"(b.x), "r"(b.y));
}

// ---------------- prep: src[K][M] fp32 -> A-frag fp16 tiles (float4 loads) --
__global__ void prep_w_kernel(const float* __restrict__ src, uint4* __restrict__ dst,
                              int R, int C, int Mtiles, int Kchunks) {
    __shared__ float ts[32][132];
    int e = blockIdx.z, mt = blockIdx.y, kc = blockIdx.x;
    int tid = threadIdx.x;
    const float* sp = src + (size_t)e * R * C + (size_t)(kc * 32) * C + mt * 128;
#pragma unroll
    for (int i = 0; i < 4; i++) {
        int idx = tid + i * 256;            // 0..1023 float4s
        int kk = idx >> 5, j = idx & 31;
        float4 v = *(const float4*)(sp + (size_t)kk * C + 4 * j);
        *(float4*)&ts[kk][4 * j] = v;
    }
    __syncthreads();
    uint4* dp = dst + ((size_t)(e * Mtiles + mt) * Kchunks + kc) * 512;
#pragma unroll
    for (int i = 0; i < 2; i++) {
        int f = tid + i * 256;
        int lane = f & 31, ks = (f >> 5) & 1, mb = f >> 6;
        int r = lane >> 2, c = lane & 3;
        int kb = ks * 16 + 2 * c;
        int m0 = mb * 16 + r;
        uint4 v;
        v.x = pack2(ts[kb][m0],     ts[kb + 1][m0]);
        v.y = pack2(ts[kb][m0 + 8], ts[kb + 1][m0 + 8]);
        v.z = pack2(ts[kb + 8][m0],     ts[kb + 9][m0]);
        v.w = pack2(ts[kb + 8][m0 + 8], ts[kb + 9][m0 + 8]);
        dp[f] = v;
    }
}

// ---------------- prep: x[t][k] fp32 -> B-frag fp16 tiles (float4 loads) ----
__global__ void prep_x_kernel(const float* __restrict__ src, uint2* __restrict__ dst) {
    __shared__ float ts[128][36];
    int e = blockIdx.z, tb = blockIdx.y, kc = blockIdx.x;
    int tid = threadIdx.x;
    const float* sp = src + (size_t)e * T_ * DIN_ + (size_t)(tb * 128) * DIN_ + kc * 32;
#pragma unroll
    for (int i = 0; i < 4; i++) {
        int idx = tid + i * 256;            // 0..1023 float4s
        int tt = idx >> 3, j = idx & 7;
        float4 v = *(const float4*)(sp + (size_t)tt * DIN_ + 4 * j);
        *(float4*)&ts[tt][4 * j] = v;
    }
    __syncthreads();
    uint2* dp = dst + ((size_t)(e * TTILES + tb) * KC1 + kc) * 1024;
#pragma unroll
    for (int i = 0; i < 4; i++) {
        int f = tid + i * 256;
        int lane = f & 31, ks = (f >> 5) & 1, n8 = f >> 6;
        int rl = lane >> 2, c = lane & 3;
        int tt = n8 * 8 + rl, kb = ks * 16 + 2 * c;
        uint2 v;
        v.x = pack2(ts[tt][kb],     ts[tt][kb + 1]);
        v.y = pack2(ts[tt][kb + 8], ts[tt][kb + 9]);
        dp[f] = v;
    }
}

// ---------------- k1: fused gate+down GEMM + SwiGLU -> h frag (fp16) --------
// 256 threads, warp grid 2(M)x4(N), warp tile 64x32 per GEMM, K-chunk 64.
// 4-stage cp.async pipeline, ONE barrier per chunk, R11 ordering (fill after
// compute). smem per stage: Ag(16KB) Ad(16KB) B(16KB) = 48KB; 4 stages = 192KB
#define K1_STAGE_U 12288
__global__ __launch_bounds__(256, 1) void k1_gemm(const uint32_t* __restrict__ xf,
                                                  const uint32_t* __restrict__ gF,
                                                  const uint32_t* __restrict__ dF,
                                                  uint32_t* __restrict__ hf) {
    extern __shared__ uint32_t sm[];
    int tid = threadIdx.x, lane = tid & 31, wid = tid >> 5;
    int wm = wid & 1, wn = wid >> 1;        // 2(M) x 4(N), warp tile 64x32
    int r = lane >> 2, c = lane & 3;

    int bid = blockIdx.x;
    int e = bid / (HTILES * TTILES);
    int rem = bid % (HTILES * TTILES);
    int ht = rem >> 4;
    int tb = rem & 15;
    int h0 = ht * 128;

    const uint32_t* gp = gF + ((size_t)(e * HTILES + ht) * KC1) * ATILE_U;
    const uint32_t* dp = dF + ((size_t)(e * HTILES + ht) * KC1) * ATILE_U;
    const uint32_t* xp = xf + ((size_t)(e * TTILES + tb) * KC1) * BTILE_U;

    float ag[4][4][4], ad[4][4][4];
#pragma unroll
    for (int mt = 0; mt < 4; mt++)
#pragma unroll
        for (int nt = 0; nt < 4; nt++)
#pragma unroll
            for (int k = 0; k < 4; k++) { ag[mt][nt][k] = 0.f; ad[mt][nt][k] = 0.f; }

    uint32_t sbase = smem_u32(sm);

    auto fill = [&](int s, int kc) {   // kc = 64-K chunk index, s = stage 0..3
        uint32_t stb = sbase + (uint32_t)(s * K1_STAGE_U * 4);
        const uint4* ga = (const uint4*)(gp + (size_t)(2 * kc) * ATILE_U);
        const uint4* da = (const uint4*)(dp + (size_t)(2 * kc) * ATILE_U);
        const uint4* xa = (const uint4*)(xp + (size_t)(2 * kc) * BTILE_U);
#pragma unroll
        for (int i = 0; i < 12; i++) {
            int idx = tid + i * 256;                 // 0..3071 uint4s
            if (idx < 1024)       cp16(stb + idx * 16, ga + idx);
            else if (idx < 2048)  cp16(stb + idx * 16, da + (idx - 1024));
            else                  cp16(stb + idx * 16, xa + (idx - 2048));
        }
    };

    auto compute = [&](int s) {
        const uint32_t* stg = sm + s * K1_STAGE_U;
        const uint4* Ag = (const uint4*)stg;               // 1024 uint4 (2 K32 subtiles)
        const uint4* Ad = (const uint4*)(stg + 4096);
        const uint2* Bx = (const uint2*)(stg + 8192);      // 2048 uint2

        // Preload ALL B fragments for the K64 chunk (4 steps x 4 nt = 32 regs)
        uint2 bf[4][4];
#pragma unroll
        for (int st = 0; st < 4; st++) {
            int kt = st >> 1, ks = st & 1;
#pragma unroll
            for (int nt = 0; nt < 4; nt++)
                bf[st][nt] = Bx[kt * 1024 + ((wn * 4 + nt) * 2 + ks) * 32 + lane];
        }
        // Preload gate-A for step 0
        uint4 aG[4], aD[4];
#pragma unroll
        for (int mt = 0; mt < 4; mt++)
            aG[mt] = Ag[((wm * 4 + mt) * 2 + 0) * 32 + lane];

#pragma unroll
        for (int st = 0; st < 4; st++) {
            int kt = st >> 1, ks = st & 1;
#pragma unroll
            for (int mt = 0; mt < 4; mt++)
                aD[mt] = Ad[kt * 512 + ((wm * 4 + mt) * 2 + ks) * 32 + lane];
#pragma unroll
            for (int mt = 0; mt < 4; mt++)
#pragma unroll
                for (int nt = 0; nt < 4; nt++) mma16(ag[mt][nt], aG[mt], bf[st][nt]);
            if (st < 3) {
                int st2 = st + 1, kt2 = st2 >> 1, ks2 = st2 & 1;
#pragma unroll
                for (int mt = 0; mt < 4; mt++)
                    aG[mt] = Ag[kt2 * 512 + ((wm * 4 + mt) * 2 + ks2) * 32 + lane];
            }
#pragma unroll
            for (int mt = 0; mt < 4; mt++)
#pragma unroll
                for (int nt = 0; nt < 4; nt++) mma16(ad[mt][nt], aD[mt], bf[st][nt]);
        }
    };

    // 4-stage pipeline, one barrier per chunk, champion (R11) ordering.
    // WAR: fill(kc+3) targets stage (kc+3)&3 == (kc-1)&3, read by compute(kc-1);
    // every thread passed barrier(kc) after compute(kc-1) -> race-free.
    // RAW: at iter kc, fills kc+1,kc+2 may be outstanding -> wait_group(2)
    // guarantees fill(kc) complete (tail narrows to 1 then 0).
    fill(0, 0); CP_COMMIT();
    fill(1, 1); CP_COMMIT();
    fill(2, 2); CP_COMMIT();
    for (int kc = 0; kc < NCH1; kc++) {
        if (kc < NCH1 - 2)       { CP_WAIT(2); }
        else if (kc == NCH1 - 2) { CP_WAIT(1); }
        else                     { CP_WAIT(0); }
        __syncthreads();
        compute(kc & 3);
        if (kc + 3 < NCH1) { fill((kc + 3) & 3, kc + 3); CP_COMMIT(); }
    }

    // SwiGLU epilogue -> hf in k2 B-frag fp16 layout (validated R7-R11).
    uint32_t* hb = hf + ((size_t)(e * TTILES + tb) * KC2) * BTILE_U;
#pragma unroll
    for (int mt = 0; mt < 4; mt++) {
        int kc2 = (h0 >> 5) + wm * 2 + (mt >> 1);
        int ks2 = mt & 1;
        uint32_t* base = hb + (size_t)kc2 * BTILE_U;
#pragma unroll
        for (int nt = 0; nt < 4; nt++) {
            int n8 = wn * 4 + nt;
#pragma unroll
            for (int q = 0; q < 4; q++) {
                float g = ag[mt][nt][q], u = ad[mt][nt][q];
                float v = g / (1.0f + __expf(-g)) * u;
                float pv = __shfl_xor_sync(0xffffffffu, v, 4);   // partner: r^1
                if (!(r & 1)) {
                    int lane2 = (2 * c + (q & 1)) * 4 + (r >> 1);
                    int fidx = (n8 * 2 + ks2) * 32 + lane2;
                    base[fidx * 2 + (q >> 1)] = pack2(v, pv);
                }
            }
        }
    }
}

// ---------------- k2: out[t,d] = sum_h h[t,h] * up[h,d] --------------------
// 256 threads, 2(M)x4(N) grid, warp tile 64x32, K-chunk 32, occ 2, 4-stage,
// champion ordering. smem 4x16KB = 64KB x2 CTAs = 128KB/SM.
#define K2_STAGE_U 4096
__global__ __launch_bounds__(256, 2) void k2_gemm(const uint32_t* __restrict__ hf,
                                                  const uint32_t* __restrict__ uF,
                                                  float* __restrict__ out) {
    extern __shared__ uint32_t sm[];
    int tid = threadIdx.x, lane = tid & 31, wid = tid >> 5;
    int wm = wid & 1, wn = wid >> 1;
    int r = lane >> 2, c = lane & 3;

    int bid = blockIdx.x;
    int e = bid / (DTILES * TTILES);
    int rem = bid % (DTILES * TTILES);
    int dt = rem >> 4;
    int tb = rem & 15;
    int d0 = dt * 128, t0 = tb * 128;

    const uint32_t* up = uF + ((size_t)(e * DTILES + dt) * KC2) * ATILE_U;
    const uint32_t* hp = hf + ((size_t)(e * TTILES + tb) * KC2) * BTILE_U;

    float acc[4][4][4];
#pragma unroll
    for (int mt = 0; mt < 4; mt++)
#pragma unroll
        for (int nt = 0; nt < 4; nt++)
#pragma unroll
            for (int k = 0; k < 4; k++) acc[mt][nt][k] = 0.f;

    uint32_t sbase = smem_u32(sm);

    auto fill = [&](int s, int kc) {
        uint32_t stb = sbase + (uint32_t)(s * K2_STAGE_U * 4);
        const uint4* ua = (const uint4*)(up + (size_t)kc * ATILE_U);
        const uint4* ha = (const uint4*)(hp + (size_t)kc * BTILE_U);
#pragma unroll
        for (int i = 0; i < 4; i++) {
            int idx = tid + i * 256;                 // 0..1023 uint4s
            if (idx < 512) cp16(stb + idx * 16, ua + idx);
            else           cp16(stb + idx * 16, ha + (idx - 512));
        }
    };

    auto compute = [&](int s) {
        const uint32_t* stg = sm + s * K2_STAGE_U;
        const uint4* A = (const uint4*)stg;
        const uint2* B = (const uint2*)(stg + 2048);
#pragma unroll
        for (int ks = 0; ks < 2; ks++) {
            uint2 bf[4];
#pragma unroll
            for (int nt = 0; nt < 4; nt++)
                bf[nt] = B[((wn * 4 + nt) * 2 + ks) * 32 + lane];
            uint4 af[4];
#pragma unroll
            for (int mt = 0; mt < 4; mt++)
                af[mt] = A[((wm * 4 + mt) * 2 + ks) * 32 + lane];
#pragma unroll
            for (int mt = 0; mt < 4; mt++)
#pragma unroll
                for (int nt = 0; nt < 4; nt++) mma16(acc[mt][nt], af[mt], bf[nt]);
        }
    };

    fill(0, 0); CP_COMMIT();
    fill(1, 1); CP_COMMIT();
    fill(2, 2); CP_COMMIT();
    for (int kc = 0; kc < KC2; kc++) {
        if (kc < KC2 - 2)       { CP_WAIT(2); }
        else if (kc == KC2 - 2) { CP_WAIT(1); }
        else                    { CP_WAIT(0); }
        __syncthreads();
        compute(kc & 3);
        if (kc + 3 < KC2) { fill((kc + 3) & 3, kc + 3); CP_COMMIT(); }
    }

    float* ob = out + (size_t)e * T_ * DIN_;
#pragma unroll
    for (int mt = 0; mt < 4; mt++)
#pragma unroll
        for (int nt = 0; nt < 4; nt++) {
            int t = t0 + (wn * 4 + nt) * 8 + 2 * c;
#pragma unroll
            for (int h2 = 0; h2 < 2; h2++) {
                int dg = d0 + wm * 64 + mt * 16 + r + h2 * 8;
                ob[(size_t)t * DIN_ + dg]       = acc[mt][nt][h2 * 2 + 0];
                ob[(size_t)(t + 1) * DIN_ + dg] = acc[mt][nt][h2 * 2 + 1];
            }
        }
}

// ---------------- launch ----------------
extern "C" void kernel_launch(void* const* d_in, const int* in_sizes, int n_in,
                              void* d_out, int out_size) {
    const float* x    = (const float*)d_in[0];
    const float* gate = (const float*)d_in[1];
    const float* down = (const float*)d_in[2];
    const float* up   = (const float*)d_in[3];
    float* out = (float*)d_out;

    uint32_t *gF, *dF, *uF, *xF, *hF;
    cudaGetSymbolAddress((void**)&gF, g_wfG);
    cudaGetSymbolAddress((void**)&dF, g_wfD);
    cudaGetSymbolAddress((void**)&uF, g_wfU);
    cudaGetSymbolAddress((void**)&xF, g_xf);
    cudaGetSymbolAddress((void**)&hF, g_hf);

    const int k1_smem = 4 * K1_STAGE_U * 4;   // 196608
    const int k2_smem = 4 * K2_STAGE_U * 4;   // 65536 (x2 CTAs = 128KB/SM)
    cudaFuncSetAttribute(k1_gemm, cudaFuncAttributeMaxDynamicSharedMemorySize, k1_smem);
    cudaFuncSetAttribute(k2_gemm, cudaFuncAttributeMaxDynamicSharedMemorySize, k2_smem);

    // keep k1 at launch index 3 (ncu's profiled slot)
    prep_w_kernel<<<dim3(KC1, HTILES, E_), 256>>>(gate, (uint4*)gF, DIN_, H_, HTILES, KC1);
    prep_w_kernel<<<dim3(KC1, HTILES, E_), 256>>>(down, (uint4*)dF, DIN_, H_, HTILES, KC1);
    prep_x_kernel<<<dim3(KC1, TTILES, E_), 256>>>(x, (uint2*)xF);
    k1_gemm<<<E_ * HTILES * TTILES, 256, k1_smem>>>(xF, gF, dF, hF);
    prep_w_kernel<<<dim3(KC2, DTILES, E_), 256>>>(up, (uint4*)uF, H_, DIN_, DTILES, KC2);
    k2_gemm<<<E_ * DTILES * TTILES, 256, k2_smem>>>(hF, uF, out);
}